// round 9
// baseline (speedup 1.0000x reference)
#include <cuda_runtime.h>

#define NXD 1024
#define NYD 1024
#define BD  16
#define NP  (NXD * NYD)

// boundary point count: y in {0..3,1020..1023} all x (8192) + x in {0,1023}, y in [4,1019] (2032)
#define NBPTS   10224
#define NBTHR   (NBPTS * BD)          // 163584
#define NB_BLK  (NBTHR / 128)         // 1278 (exact)
#define NI_BLK  2048                  // 8 qcols x 256 xrows

// ---- generic stencil helpers (boundary path) ----
__device__ __forceinline__ void gcoef1(int i, int N, int idx[3], float c[3], int& n) {
    if (i == 0)          { idx[0]=0;   idx[1]=1;   idx[2]=2;   c[0]=-1.5f; c[1]= 2.0f; c[2]=-0.5f; n=3; }
    else if (i == N - 1) { idx[0]=N-1; idx[1]=N-2; idx[2]=N-3; c[0]= 1.5f; c[1]=-2.0f; c[2]= 0.5f; n=3; }
    else                 { idx[0]=i-1; idx[1]=i+1; c[0]=-0.5f; c[1]=0.5f; n=2; }
}

__device__ __forceinline__ void gcoef2(int i, int N, int idx[4], float c[4], int& n) {
    if (i == 0)          { idx[0]=0;   idx[1]=1;   idx[2]=2;   idx[3]=3;   c[0]=2.0f; c[1]=-5.0f; c[2]=4.0f; c[3]=-1.0f; n=4; }
    else if (i == N - 1) { idx[0]=N-1; idx[1]=N-2; idx[2]=N-3; idx[3]=N-4; c[0]=2.0f; c[1]=-5.0f; c[2]=4.0f; c[3]=-1.0f; n=4; }
    else                 { idx[0]=i-1; idx[1]=i;   idx[2]=i+1; c[0]=1.0f; c[1]=-2.0f; c[2]=1.0f; n=3; }
}

__device__ __noinline__ float generic_df(const float* __restrict__ Fb,
                            const float* __restrict__ A0, const float* __restrict__ A1,
                            const float* __restrict__ B0, const float* __restrict__ B1,
                            const float* __restrict__ B2, int x, int y)
{
    int ix1[3]; float cx1[3]; int nx1;
    int iy1[3]; float cy1[3]; int ny1;
    gcoef1(x, NXD, ix1, cx1, nx1);
    gcoef1(y, NYD, iy1, cy1, ny1);

    int ix2[4]; float cx2[4]; int nx2;
    int iy2[4]; float cy2[4]; int ny2;
    gcoef2(x, NXD, ix2, cx2, nx2);
    gcoef2(y, NYD, iy2, cy2, ny2);

    float ga = 0.0f;
    #pragma unroll
    for (int j = 0; j < 3; ++j)
        if (j < nx1) { int k = ix1[j] * NYD + y; ga += cx1[j] * __ldg(&A0[k]) * __ldg(&Fb[k]); }
    #pragma unroll
    for (int j = 0; j < 3; ++j)
        if (j < ny1) { int k = x * NYD + iy1[j]; ga += cy1[j] * __ldg(&A1[k]) * __ldg(&Fb[k]); }

    float gb = 0.0f;
    #pragma unroll
    for (int j = 0; j < 4; ++j)
        if (j < nx2) { int k = ix2[j] * NYD + y; gb += cx2[j] * __ldg(&B0[k]) * __ldg(&Fb[k]); }
    #pragma unroll
    for (int j = 0; j < 4; ++j)
        if (j < ny2) { int k = x * NYD + iy2[j]; gb += cy2[j] * __ldg(&B1[k]) * __ldg(&Fb[k]); }

    float gc = 0.0f;
    #pragma unroll
    for (int j = 0; j < 3; ++j)
        if (j < nx1) {
            float acc = 0.0f;
            #pragma unroll
            for (int k = 0; k < 3; ++k)
                if (k < ny1) {
                    int idx = ix1[j] * NYD + iy1[k];
                    acc += cy1[k] * __ldg(&B2[idx]) * __ldg(&Fb[idx]);
                }
            gc += cx1[j] * acc;
        }
    return -ga + 0.5f * gb + gc;
}

// ================= fused kernel =================
// blocks [0, NB_BLK)             : boundary points (scheduled first, overlap)
// blocks [NB_BLK, NB_BLK+NI_BLK) : interior, shuffle-halo fast path
__global__ void __launch_bounds__(128, 6) fp2d_fused(
    const float* __restrict__ f,      // [B, NX, NY]
    const float* __restrict__ Agrid,  // [2, NX, NY]
    const float* __restrict__ Bgrid,  // [3, NX, NY]
    const float* __restrict__ dt,     // [B]
    float* __restrict__ out)          // [B, NX, NY]
{
    const float* __restrict__ A0 = Agrid;
    const float* __restrict__ A1 = Agrid + NP;
    const float* __restrict__ B0 = Bgrid;
    const float* __restrict__ B1 = Bgrid + NP;
    const float* __restrict__ B2 = Bgrid + 2 * NP;

    const int bid = blockIdx.x;

    if (bid < NB_BLK) {
        // ---------------- boundary path ----------------
        const int t = bid * 128 + threadIdx.x;     // < NBTHR exactly
        const int b   = t / NBPTS;
        const int idx = t - b * NBPTS;
        int x, y;
        if (idx < 8192) {
            x = idx >> 3;
            int r = idx & 7;
            y = (r < 4) ? r : (1016 + r);
        } else {
            int r = idx - 8192;
            x = (r & 1) ? 1023 : 0;
            y = 4 + (r >> 1);
        }
        const float* __restrict__ Fb = f + b * NP;
        const float df = generic_df(Fb, A0, A1, B0, B1, B2, x, y);
        const int k = x * NYD + y;
        float v = fmaf(df, __ldg(&dt[b]), __ldg(&Fb[k]));
        out[b * NP + k] = fmaxf(v, 0.0f);
        return;
    }

    // ---------------- interior path ----------------
    const int ib   = bid - NB_BLK;
    const int bx   = ib & 7;               // 0..7  -> quad column group
    const int by   = ib >> 3;              // 0..255 -> x row group
    const int lane = threadIdx.x & 31;
    const int ty   = threadIdx.x >> 5;

    const int q  = bx * 32 + lane;         // 0..255, all lanes active
    const int x  = 1 + by * 4 + ty;
    if (x > 1022) return;                  // warp-uniform (ty per warp)
    const int y0 = q * 4;

    // edge-lane halo offsets; clamped for q==0 / q==255 (those quads' outputs
    // are wholly owned by the boundary path and NOT stored here)
    const int loff = (y0 == 0)    ? 0 : -1;
    const int roff = (y0 == 1020) ? 3 : 4;
    const bool do_store = (q != 0) && (q != 255);

    const int bm = (x - 1) * NYD + y0;
    const int bc =  x      * NYD + y0;
    const int bp = (x + 1) * NYD + y0;

    // ---- batch-invariant grid values: float4 + 2 clamped scalars per row ----
    float b2m[6], b2p[6], a1v[6], b1v[6];
    {
        float4 m;
        m = __ldg((const float4*)&B2[bm]);
        b2m[0]=__ldg(&B2[bm+loff]); b2m[1]=m.x; b2m[2]=m.y; b2m[3]=m.z; b2m[4]=m.w; b2m[5]=__ldg(&B2[bm+roff]);
        m = __ldg((const float4*)&B2[bp]);
        b2p[0]=__ldg(&B2[bp+loff]); b2p[1]=m.x; b2p[2]=m.y; b2p[3]=m.z; b2p[4]=m.w; b2p[5]=__ldg(&B2[bp+roff]);
        m = __ldg((const float4*)&A1[bc]);
        a1v[0]=__ldg(&A1[bc+loff]); a1v[1]=m.x; a1v[2]=m.y; a1v[3]=m.z; a1v[4]=m.w; a1v[5]=__ldg(&A1[bc+roff]);
        m = __ldg((const float4*)&B1[bc]);
        b1v[0]=__ldg(&B1[bc+loff]); b1v[1]=m.x; b1v[2]=m.y; b1v[3]=m.z; b1v[4]=m.w; b1v[5]=__ldg(&B1[bc+roff]);
    }
    const float4 a0m = __ldg((const float4*)&A0[bm]);
    const float4 a0p = __ldg((const float4*)&A0[bp]);
    const float4 b0m = __ldg((const float4*)&B0[bm]);
    const float4 b0c = __ldg((const float4*)&B0[bc]);
    const float4 b0p = __ldg((const float4*)&B0[bp]);

    // ---- fold into 9 weights per point ----
    float wmm[4], wm0[4], wmp[4], w0m[4], w00[4], w0p[4], wpm[4], wp0[4], wpp[4];
    {
        const float a0ma[4] = {a0m.x, a0m.y, a0m.z, a0m.w};
        const float a0pa[4] = {a0p.x, a0p.y, a0p.z, a0p.w};
        const float b0ma[4] = {b0m.x, b0m.y, b0m.z, b0m.w};
        const float b0ca[4] = {b0c.x, b0c.y, b0c.z, b0c.w};
        const float b0pa[4] = {b0p.x, b0p.y, b0p.z, b0p.w};
        #pragma unroll
        for (int s = 0; s < 4; ++s) {
            wmm[s] =  0.25f * b2m[s];
            wmp[s] = -0.25f * b2m[s + 2];
            wpm[s] = -0.25f * b2p[s];
            wpp[s] =  0.25f * b2p[s + 2];
            w0m[s] =  0.5f * (a1v[s] + b1v[s]);
            w0p[s] =  0.5f * (b1v[s + 2] - a1v[s + 2]);
            wm0[s] =  0.5f * (a0ma[s] + b0ma[s]);
            wp0[s] =  0.5f * (b0pa[s] - a0pa[s]);
            w00[s] = -(b0ca[s] + b1v[s + 1]);
        }
    }

    const unsigned FULL = 0xffffffffu;
    const float* __restrict__ Fb = f;
    float* __restrict__ Ob = out + bc;

    for (int b = 0; b < BD; ++b, Fb += NP, Ob += NP) {
        const float dtb = __ldg(&dt[b]);

        float4 vm = __ldg((const float4*)&Fb[bm]);
        float4 vc = __ldg((const float4*)&Fb[bc]);
        float4 vp = __ldg((const float4*)&Fb[bp]);

        float Lm = __shfl_up_sync(FULL, vm.w, 1);
        float Lc = __shfl_up_sync(FULL, vc.w, 1);
        float Lp = __shfl_up_sync(FULL, vp.w, 1);
        float Rm = __shfl_down_sync(FULL, vm.x, 1);
        float Rc = __shfl_down_sync(FULL, vc.x, 1);
        float Rp = __shfl_down_sync(FULL, vp.x, 1);
        if (lane == 0) {
            Lm = __ldg(&Fb[bm + loff]);
            Lc = __ldg(&Fb[bc + loff]);
            Lp = __ldg(&Fb[bp + loff]);
        }
        if (lane == 31) {
            Rm = __ldg(&Fb[bm + roff]);
            Rc = __ldg(&Fb[bc + roff]);
            Rp = __ldg(&Fb[bp + roff]);
        }

        const float dm[6] = {Lm, vm.x, vm.y, vm.z, vm.w, Rm};
        const float dc[6] = {Lc, vc.x, vc.y, vc.z, vc.w, Rc};
        const float dp[6] = {Lp, vp.x, vp.y, vp.z, vp.w, Rp};

        float o[4];
        #pragma unroll
        for (int s = 0; s < 4; ++s) {
            float df;
            df = wmm[s] * dm[s];
            df = fmaf(wm0[s], dm[s + 1], df);
            df = fmaf(wmp[s], dm[s + 2], df);
            df = fmaf(w0m[s], dc[s],     df);
            df = fmaf(w00[s], dc[s + 1], df);
            df = fmaf(w0p[s], dc[s + 2], df);
            df = fmaf(wpm[s], dp[s],     df);
            df = fmaf(wp0[s], dp[s + 1], df);
            df = fmaf(wpp[s], dp[s + 2], df);
            o[s] = fmaxf(fmaf(df, dtb, dc[s + 1]), 0.0f);
        }
        if (do_store)
            *(float4*)Ob = make_float4(o[0], o[1], o[2], o[3]);
    }
}

extern "C" void kernel_launch(void* const* d_in, const int* in_sizes, int n_in,
                              void* d_out, int out_size) {
    const float* f  = (const float*)d_in[0];
    const float* Ag = (const float*)d_in[1];
    const float* Bg = (const float*)d_in[2];
    const float* dt = (const float*)d_in[3];
    float* out = (float*)d_out;

    fp2d_fused<<<NB_BLK + NI_BLK, 128>>>(f, Ag, Bg, dt, out);
}

// round 10
// speedup vs baseline: 1.3672x; 1.3672x over previous
#include <cuda_runtime.h>

#define NXD 1024
#define NYD 1024
#define BD  16
#define NP  (NXD * NYD)

// boundary: y in {0..3,1020..1023} all x (8192) + x in {0,1023}, y in [4,1019] (2032)
#define NBPTS   10224
#define NBTHR   (NBPTS * BD)          // 163584
#define NB_BLK  (NBTHR / 128)         // 1278 (exact)
#define NI_BLK  2048                  // 8 quad-col groups x 256 x-row groups

// ---- generic stencil helpers (boundary path) ----
__device__ __forceinline__ void gcoef1(int i, int N, int idx[3], float c[3], int& n) {
    if (i == 0)          { idx[0]=0;   idx[1]=1;   idx[2]=2;   c[0]=-1.5f; c[1]= 2.0f; c[2]=-0.5f; n=3; }
    else if (i == N - 1) { idx[0]=N-1; idx[1]=N-2; idx[2]=N-3; c[0]= 1.5f; c[1]=-2.0f; c[2]= 0.5f; n=3; }
    else                 { idx[0]=i-1; idx[1]=i+1; c[0]=-0.5f; c[1]=0.5f; n=2; }
}

__device__ __forceinline__ void gcoef2(int i, int N, int idx[4], float c[4], int& n) {
    if (i == 0)          { idx[0]=0;   idx[1]=1;   idx[2]=2;   idx[3]=3;   c[0]=2.0f; c[1]=-5.0f; c[2]=4.0f; c[3]=-1.0f; n=4; }
    else if (i == N - 1) { idx[0]=N-1; idx[1]=N-2; idx[2]=N-3; idx[3]=N-4; c[0]=2.0f; c[1]=-5.0f; c[2]=4.0f; c[3]=-1.0f; n=4; }
    else                 { idx[0]=i-1; idx[1]=i;   idx[2]=i+1; c[0]=1.0f; c[1]=-2.0f; c[2]=1.0f; n=3; }
}

__device__ __noinline__ float generic_df(const float* __restrict__ Fb,
                            const float* __restrict__ A0, const float* __restrict__ A1,
                            const float* __restrict__ B0, const float* __restrict__ B1,
                            const float* __restrict__ B2, int x, int y)
{
    int ix1[3]; float cx1[3]; int nx1;
    int iy1[3]; float cy1[3]; int ny1;
    gcoef1(x, NXD, ix1, cx1, nx1);
    gcoef1(y, NYD, iy1, cy1, ny1);

    int ix2[4]; float cx2[4]; int nx2;
    int iy2[4]; float cy2[4]; int ny2;
    gcoef2(x, NXD, ix2, cx2, nx2);
    gcoef2(y, NYD, iy2, cy2, ny2);

    float ga = 0.0f;
    #pragma unroll
    for (int j = 0; j < 3; ++j)
        if (j < nx1) { int k = ix1[j] * NYD + y; ga += cx1[j] * __ldg(&A0[k]) * __ldg(&Fb[k]); }
    #pragma unroll
    for (int j = 0; j < 3; ++j)
        if (j < ny1) { int k = x * NYD + iy1[j]; ga += cy1[j] * __ldg(&A1[k]) * __ldg(&Fb[k]); }

    float gb = 0.0f;
    #pragma unroll
    for (int j = 0; j < 4; ++j)
        if (j < nx2) { int k = ix2[j] * NYD + y; gb += cx2[j] * __ldg(&B0[k]) * __ldg(&Fb[k]); }
    #pragma unroll
    for (int j = 0; j < 4; ++j)
        if (j < ny2) { int k = x * NYD + iy2[j]; gb += cy2[j] * __ldg(&B1[k]) * __ldg(&Fb[k]); }

    float gc = 0.0f;
    #pragma unroll
    for (int j = 0; j < 3; ++j)
        if (j < nx1) {
            float acc = 0.0f;
            #pragma unroll
            for (int k = 0; k < 3; ++k)
                if (k < ny1) {
                    int idx = ix1[j] * NYD + iy1[k];
                    acc += cy1[k] * __ldg(&B2[idx]) * __ldg(&Fb[idx]);
                }
            gc += cx1[j] * acc;
        }
    return -ga + 0.5f * gb + gc;
}

// ================= fused kernel =================
// blocks [0, NB_BLK)             : boundary points (co-scheduled with interior)
// blocks [NB_BLK, NB_BLK+NI_BLK) : interior, R7-style vector-load fast path
__global__ void __launch_bounds__(128, 6) fp2d_fused(
    const float* __restrict__ f,      // [B, NX, NY]
    const float* __restrict__ Agrid,  // [2, NX, NY]
    const float* __restrict__ Bgrid,  // [3, NX, NY]
    const float* __restrict__ dt,     // [B]
    float* __restrict__ out)          // [B, NX, NY]
{
    const float* __restrict__ A0 = Agrid;
    const float* __restrict__ A1 = Agrid + NP;
    const float* __restrict__ B0 = Bgrid;
    const float* __restrict__ B1 = Bgrid + NP;
    const float* __restrict__ B2 = Bgrid + 2 * NP;

    const int bid = blockIdx.x;

    if (bid < NB_BLK) {
        // ---------------- boundary path ----------------
        const int t = bid * 128 + threadIdx.x;     // < NBTHR exactly
        const int b   = t / NBPTS;
        const int idx = t - b * NBPTS;
        int x, y;
        if (idx < 8192) {
            x = idx >> 3;
            int r = idx & 7;
            y = (r < 4) ? r : (1016 + r);
        } else {
            int r = idx - 8192;
            x = (r & 1) ? 1023 : 0;
            y = 4 + (r >> 1);
        }
        const float* __restrict__ Fb = f + b * NP;
        const float df = generic_df(Fb, A0, A1, B0, B1, B2, x, y);
        const int k = x * NYD + y;
        float v = fmaf(df, __ldg(&dt[b]), __ldg(&Fb[k]));
        out[b * NP + k] = fmaxf(v, 0.0f);
        return;
    }

    // ---------------- interior path (R7 body) ----------------
    const int ib = bid - NB_BLK;
    const int bx = ib & 7;                    // 0..7   quad-column group
    const int by = ib >> 3;                   // 0..255 x-row group
    const int q  = 1 + bx * 32 + (threadIdx.x & 31);   // want [1,254]
    const int x  = 1 + by * 4 + (threadIdx.x >> 5);    // want [1,1022]
    if (q > 254 || x > 1022) return;
    const int y0 = q * 4;                     // y0 in [4,1016], 16B aligned

    const int bm = (x - 1) * NYD + y0;
    const int bc =  x      * NYD + y0;
    const int bp = (x + 1) * NYD + y0;

    // ---- batch-invariant grid loads: 6-val rows as float2 + float4 + float2 ----
    float b2m[6], b2p[6], a1v[6], b1v[6];
    {
        float2 e0; float4 m; float2 e1;
        e0 = __ldg((const float2*)&B2[bm - 2]); m = __ldg((const float4*)&B2[bm]); e1 = __ldg((const float2*)&B2[bm + 4]);
        b2m[0]=e0.y; b2m[1]=m.x; b2m[2]=m.y; b2m[3]=m.z; b2m[4]=m.w; b2m[5]=e1.x;
        e0 = __ldg((const float2*)&B2[bp - 2]); m = __ldg((const float4*)&B2[bp]); e1 = __ldg((const float2*)&B2[bp + 4]);
        b2p[0]=e0.y; b2p[1]=m.x; b2p[2]=m.y; b2p[3]=m.z; b2p[4]=m.w; b2p[5]=e1.x;
        e0 = __ldg((const float2*)&A1[bc - 2]); m = __ldg((const float4*)&A1[bc]); e1 = __ldg((const float2*)&A1[bc + 4]);
        a1v[0]=e0.y; a1v[1]=m.x; a1v[2]=m.y; a1v[3]=m.z; a1v[4]=m.w; a1v[5]=e1.x;
        e0 = __ldg((const float2*)&B1[bc - 2]); m = __ldg((const float4*)&B1[bc]); e1 = __ldg((const float2*)&B1[bc + 4]);
        b1v[0]=e0.y; b1v[1]=m.x; b1v[2]=m.y; b1v[3]=m.z; b1v[4]=m.w; b1v[5]=e1.x;
    }
    const float4 a0m = __ldg((const float4*)&A0[bm]);
    const float4 a0p = __ldg((const float4*)&A0[bp]);
    const float4 b0m = __ldg((const float4*)&B0[bm]);
    const float4 b0c = __ldg((const float4*)&B0[bc]);
    const float4 b0p = __ldg((const float4*)&B0[bp]);

    // ---- fold into 9 weights per point ----
    float wmm[4], wm0[4], wmp[4], w0m[4], w00[4], w0p[4], wpm[4], wp0[4], wpp[4];
    {
        const float a0ma[4] = {a0m.x, a0m.y, a0m.z, a0m.w};
        const float a0pa[4] = {a0p.x, a0p.y, a0p.z, a0p.w};
        const float b0ma[4] = {b0m.x, b0m.y, b0m.z, b0m.w};
        const float b0ca[4] = {b0c.x, b0c.y, b0c.z, b0c.w};
        const float b0pa[4] = {b0p.x, b0p.y, b0p.z, b0p.w};
        #pragma unroll
        for (int s = 0; s < 4; ++s) {
            wmm[s] =  0.25f * b2m[s];
            wmp[s] = -0.25f * b2m[s + 2];
            wpm[s] = -0.25f * b2p[s];
            wpp[s] =  0.25f * b2p[s + 2];
            w0m[s] =  0.5f * (a1v[s] + b1v[s]);
            w0p[s] =  0.5f * (b1v[s + 2] - a1v[s + 2]);
            wm0[s] =  0.5f * (a0ma[s] + b0ma[s]);
            wp0[s] =  0.5f * (b0pa[s] - a0pa[s]);
            w00[s] = -(b0ca[s] + b1v[s + 1]);
        }
    }

    // ---- batch loop: 9 vector loads -> 36 FMA -> 1 STG.128 ----
    const float* __restrict__ Fb = f;
    float* __restrict__ Ob = out + bc;
    for (int b = 0; b < BD; ++b, Fb += NP, Ob += NP) {
        const float dtb = __ldg(&dt[b]);

        float2 m2 = __ldg((const float2*)&Fb[bm - 2]);
        float4 m4 = __ldg((const float4*)&Fb[bm]);
        float2 m6 = __ldg((const float2*)&Fb[bm + 4]);
        float2 c2 = __ldg((const float2*)&Fb[bc - 2]);
        float4 c4 = __ldg((const float4*)&Fb[bc]);
        float2 c6 = __ldg((const float2*)&Fb[bc + 4]);
        float2 p2 = __ldg((const float2*)&Fb[bp - 2]);
        float4 p4 = __ldg((const float4*)&Fb[bp]);
        float2 p6 = __ldg((const float2*)&Fb[bp + 4]);

        const float dm[6] = {m2.y, m4.x, m4.y, m4.z, m4.w, m6.x};
        const float dc[6] = {c2.y, c4.x, c4.y, c4.z, c4.w, c6.x};
        const float dp[6] = {p2.y, p4.x, p4.y, p4.z, p4.w, p6.x};

        float o[4];
        #pragma unroll
        for (int s = 0; s < 4; ++s) {
            float df;
            df = wmm[s] * dm[s];
            df = fmaf(wm0[s], dm[s + 1], df);
            df = fmaf(wmp[s], dm[s + 2], df);
            df = fmaf(w0m[s], dc[s],     df);
            df = fmaf(w00[s], dc[s + 1], df);
            df = fmaf(w0p[s], dc[s + 2], df);
            df = fmaf(wpm[s], dp[s],     df);
            df = fmaf(wp0[s], dp[s + 1], df);
            df = fmaf(wpp[s], dp[s + 2], df);
            o[s] = fmaxf(fmaf(df, dtb, dc[s + 1]), 0.0f);
        }
        *(float4*)Ob = make_float4(o[0], o[1], o[2], o[3]);
    }
}

extern "C" void kernel_launch(void* const* d_in, const int* in_sizes, int n_in,
                              void* d_out, int out_size) {
    const float* f  = (const float*)d_in[0];
    const float* Ag = (const float*)d_in[1];
    const float* Bg = (const float*)d_in[2];
    const float* dt = (const float*)d_in[3];
    float* out = (float*)d_out;

    fp2d_fused<<<NB_BLK + NI_BLK, 128>>>(f, Ag, Bg, dt, out);
}